// round 8
// baseline (speedup 1.0000x reference)
#include <cuda_runtime.h>

#define UNITS  224
#define SENS   64
#define MOTORN 32
#define CMDN   64
#define INTERN 128
#define OUTL   32
#define NB     32
#define NT     32
#define UNF    6
#define CAPS   32
#define CAPI   64
#define CAPC   16
#define CAPM   32
#define LOG2E  1.4426950408889634f
#define EPSF   1e-8f

// ---------------- compacted tables (rebuilt every launch) ----------------
__device__ float4 g_ssyn [UNITS * CAPS];   // ex2 form {s*log2e, s*mu*log2e, wm, wm*erev}
__device__ int    g_sidx [UNITS * CAPS];
__device__ int    g_scnt [UNITS];
__device__ float4 g_cisyn[CMDN * CAPI];    // ex2 form
__device__ int    g_ciix [CMDN * CAPI];
__device__ int    g_cic  [CMDN];
__device__ float4 g_ccsyn[CMDN * CAPC];    // tanh form {.5s, .5s*mu, .5wm, .5wm*erev}
__device__ int    g_ccix [CMDN * CAPC];
__device__ int    g_ccc  [CMDN];
__device__ float2 g_ccb  [CMDN];           // {sum .5wm*erev, sum .5wm}
__device__ float4 g_msyn [MOTORN * CAPM];  // ex2 form
__device__ int    g_mtix [MOTORN * CAPM];
__device__ int    g_mc   [MOTORN];
__device__ int    g_badv [UNITS];

// ---------------- scratch ----------------
__device__ float2 g_ssum [NB * NT * 96];
__device__ float2 g_iac  [NB * NT * INTERN];
__device__ float  g_vtraj[NB * NT * UNF * INTERN];
__device__ float2 g_pcmd [NB * NT * UNF * CMDN];
__device__ float  g_ctraj[NB * NT * UNF * CMDN];
__device__ float2 g_mac  [NB * NT * UNF * MOTORN];

__device__ __forceinline__ float ex2f(float x) {
    float r; asm("ex2.approx.ftz.f32 %0, %1;" : "=f"(r) : "f"(x)); return r;
}
__device__ __forceinline__ float rcpf(float x) {
    float r; asm("rcp.approx.ftz.f32 %0, %1;" : "=f"(r) : "f"(x)); return r;
}
__device__ __forceinline__ float tanhf_a(float x) {
    float r; asm("tanh.approx.f32 %0, %1;" : "=f"(r) : "f"(x)); return r;
}

// ======================= prep: one warp per post column =======================
__global__ void kprep(
    const float* __restrict__ smu,  const float* __restrict__ ssig,
    const float* __restrict__ swt,  const float* __restrict__ serev,
    const float* __restrict__ smask,
    const float* __restrict__ mu,   const float* __restrict__ sig,
    const float* __restrict__ wt,   const float* __restrict__ erev,
    const float* __restrict__ mask)
{
    const int j = blockIdx.x;
    const int lane = threadIdx.x;
    const unsigned FULL = 0xffffffffu;
    const unsigned lt = (1u << lane) - 1u;
    int bad = 0;

    float mv[7];
#pragma unroll
    for (int r = 0; r < 7; r++) mv[r] = mask[(r * 32 + lane) * UNITS + j];
    float sv[2];
#pragma unroll
    for (int r = 0; r < 2; r++) sv[r] = smask[(r * 32 + lane) * UNITS + j];

    if (j < MOTORN) {
        int cnt = 0;
#pragma unroll
        for (int r = 0; r < 7; r++) {
            const int i = r * 32 + lane, gi = i * UNITS + j;
            const bool act = (mv[r] != 0.f);
            if (act && i < MOTORN) bad = 1;
            unsigned bal = __ballot_sync(FULL, act);
            if (act) {
                int pos = cnt + __popc(bal & lt);
                if (pos < CAPM && i >= MOTORN) {
                    float sg = sig[gi], wm = wt[gi] * mv[r];
                    g_msyn[j * CAPM + pos] =
                        make_float4(sg * LOG2E, sg * mu[gi] * LOG2E, wm, wm * erev[gi]);
                    g_mtix[j * CAPM + pos] = i - MOTORN;
                }
            }
            cnt += __popc(bal);
        }
        if (cnt > CAPM) bad = 1;
        if (lane == 0) g_mc[j] = cnt;
    } else if (j < MOTORN + CMDN) {
        const int c = j - MOTORN;
        int icnt = 0, ccnt = 0;
#pragma unroll
        for (int r = 0; r < 7; r++) {
            const int i = r * 32 + lane, gi = i * UNITS + j;
            const bool act = (mv[r] != 0.f);
            if (act && i < MOTORN) bad = 1;
            const bool isI = act && (i >= MOTORN + CMDN);
            const bool isC = act && (i >= MOTORN) && (i < MOTORN + CMDN);
            unsigned balI = __ballot_sync(FULL, isI);
            unsigned balC = __ballot_sync(FULL, isC);
            if (isI) {
                int pos = icnt + __popc(balI & lt);
                if (pos < CAPI) {
                    float sg = sig[gi], wm = wt[gi] * mv[r];
                    g_cisyn[c * CAPI + pos] =
                        make_float4(sg * LOG2E, sg * mu[gi] * LOG2E, wm, wm * erev[gi]);
                    g_ciix[c * CAPI + pos] = i - (MOTORN + CMDN);
                }
            }
            if (isC) {
                int pos = ccnt + __popc(balC & lt);
                if (pos < CAPC) {
                    // tanh form: sigmoid(x) = 0.5 + 0.5*tanh(0.5*sig*(v-mu))
                    float sg = sig[gi], wm = wt[gi] * mv[r];
                    g_ccsyn[c * CAPC + pos] =
                        make_float4(0.5f * sg, 0.5f * sg * mu[gi],
                                    0.5f * wm, 0.5f * wm * erev[gi]);
                    g_ccix[c * CAPC + pos] = i - MOTORN;
                }
            }
            icnt += __popc(balI);
            ccnt += __popc(balC);
        }
        if (icnt > CAPI || ccnt > CAPC) bad = 1;
        // zero-pad cmd<-cmd table (kp3 reads padded entries; z=w=0 -> no-op)
        for (int pos = ccnt + lane; pos < CAPC; pos += 32) {
            g_ccsyn[c * CAPC + pos] = make_float4(0.f, 0.f, 0.f, 0.f);
            g_ccix[c * CAPC + pos] = 0;
        }
        if (lane == 0) { g_cic[c] = icnt; g_ccc[c] = ccnt; }
        // per-post constant part of the tanh split: sum(.5wm*erev), sum(.5wm)
        __syncwarp();
        float swre = 0.f, sw = 0.f;
        if (lane < CAPC) {
            float4 e = g_ccsyn[c * CAPC + lane];
            swre = e.w; sw = e.z;
        }
#pragma unroll
        for (int off = 16; off; off >>= 1) {
            swre += __shfl_xor_sync(FULL, swre, off);
            sw   += __shfl_xor_sync(FULL, sw, off);
        }
        if (lane == 0) g_ccb[c] = make_float2(swre, sw);
    } else {
#pragma unroll
        for (int r = 0; r < 7; r++)
            if (mv[r] != 0.f) bad = 1;   // inter posts must be recurrent-free
    }

    // sensory table (all posts)
    int cnt = 0;
#pragma unroll
    for (int r = 0; r < 2; r++) {
        const int i = r * 32 + lane, gi = i * UNITS + j;
        const bool act = (sv[r] != 0.f);
        unsigned bal = __ballot_sync(FULL, act);
        if (act) {
            int pos = cnt + __popc(bal & lt);
            if (pos < CAPS) {
                float sg = ssig[gi], wm = swt[gi] * sv[r];
                g_ssyn[j * CAPS + pos] =
                    make_float4(sg * LOG2E, sg * smu[gi] * LOG2E, wm, wm * serev[gi]);
                g_sidx[j * CAPS + pos] = i;
            }
        }
        cnt += __popc(bal);
    }
    if (cnt > CAPS) bad = 1;
    if (lane == 0) g_scnt[j] = cnt;

    bad = (__ballot_sync(FULL, bad) != 0u);
    if (lane == 0) g_badv[j] = bad;
}

// ============ P1: per-(b,s) sensory sums + inter affine coeffs (grid 1024) ====
__global__ void __launch_bounds__(256)
kp1(const float* __restrict__ inputs,
    const float* __restrict__ input_w, const float* __restrict__ input_b,
    const float* __restrict__ gleak, const float* __restrict__ vleak,
    const float* __restrict__ cm)
{
    __shared__ float sx[SENS];
    const int bs = blockIdx.x;
    const int t = threadIdx.x;
    if (t < SENS)
        sx[t] = fmaf(inputs[bs * SENS + t], input_w[t], input_b[t]);
    __syncthreads();
    if (t < UNITS) {
        const int scnt = min(g_scnt[t], CAPS);
        float sn = 0.f, sd = 0.f;
#pragma unroll 4
        for (int k = 0; k < scnt; k++) {
            float4 sy = g_ssyn[t * CAPS + k];
            float x = sx[g_sidx[t * CAPS + k]];
            float sg = rcpf(1.f + ex2f(fmaf(-sy.x, x, sy.y)));
            sd = fmaf(sy.z, sg, sd); sn = fmaf(sy.w, sg, sn);
        }
        if (t < MOTORN + CMDN) {
            g_ssum[bs * 96 + t] = make_float2(sn, sd);
        } else {
            float cmt = cm[t] * (float)UNF;
            float gl  = gleak[t];
            float dinv = rcpf(cmt + gl + sd + EPSF);
            g_iac[bs * INTERN + (t - 96)] =
                make_float2(cmt * dinv, fmaf(gl, vleak[t], sn) * dinv);
        }
    }
}

// ============ inter affine scans: grid 32 x 128 ==============================
__global__ void __launch_bounds__(INTERN)
kiscan()
{
    const int b = blockIdx.x, i = threadIdx.x;
    float v = 0.f;
    float2 ac = g_iac[(b * NT) * INTERN + i];
    for (int s = 0; s < NT; s++) {
        const int sn = (s + 1 < NT) ? s + 1 : s;
        float2 nac = g_iac[(b * NT + sn) * INTERN + i];
        const int base = ((b * NT + s) * UNF) * INTERN + i;
#pragma unroll
        for (int u = 0; u < UNF; u++) {
            g_vtraj[base + u * INTERN] = v;
            v = fmaf(ac.x, v, ac.y);
        }
        ac = nac;
    }
}

// ============ P2: cmd <- inter partials: grid 1024 x 256, k-outer ============
__global__ void __launch_bounds__(256)
kp2()
{
    __shared__ float vr[UNF][INTERN];
    const int bs = blockIdx.x;
    const int t = threadIdx.x;
    for (int i = t; i < UNF * INTERN; i += 256)
        vr[i >> 7][i & 127] = g_vtraj[bs * (UNF * INTERN) + i];
    __syncthreads();
    const int c = t >> 2, h = t & 3;
    const int cnt = min(g_cic[c], CAPI);
    float na[UNF], da[UNF];
#pragma unroll
    for (int u = 0; u < UNF; u++) { na[u] = 0.f; da[u] = 0.f; }
#pragma unroll 2
    for (int k = h; k < cnt; k += 4) {
        float4 sy = g_cisyn[c * CAPI + k];
        const int ix = g_ciix[c * CAPI + k];
#pragma unroll
        for (int u = 0; u < UNF; u++) {
            float vp = vr[u][ix];
            float sg = rcpf(1.f + ex2f(fmaf(-sy.x, vp, sy.y)));
            da[u] = fmaf(sy.z, sg, da[u]);
            na[u] = fmaf(sy.w, sg, na[u]);
        }
    }
#pragma unroll
    for (int u = 0; u < UNF; u++) {
        float nu = na[u], du = da[u];
        nu += __shfl_xor_sync(0xffffffffu, nu, 1);
        nu += __shfl_xor_sync(0xffffffffu, nu, 2);
        du += __shfl_xor_sync(0xffffffffu, du, 1);
        du += __shfl_xor_sync(0xffffffffu, du, 2);
        if (h == 0) g_pcmd[(bs * UNF + u) * CMDN + c] = make_float2(nu, du);
    }
}

// ============ P3: sequential command core: grid 32 x 32, tanh ================
__global__ void __launch_bounds__(32)
kp3(const float* __restrict__ gleak, const float* __restrict__ vleak,
    const float* __restrict__ cm)
{
    const int b = blockIdx.x;
    const int l = threadIdx.x;
    const unsigned FULL = 0xffffffffu;
    const int p0 = l, p1 = 32 + l;
    const int j0 = MOTORN + p0, j1 = MOTORN + p1;
    const float cmt0 = cm[j0] * (float)UNF, cmt1 = cm[j1] * (float)UNF;
    const float gl0 = gleak[j0], gl1 = gleak[j1];
    const float gv0 = gl0 * vleak[j0], gv1 = gl1 * vleak[j1];
    const int cc0 = min(g_ccc[p0], CAPC), cc1 = min(g_ccc[p1], CAPC);
    const float2 cb0 = g_ccb[p0], cb1 = g_ccb[p1];

    float4 syA[8]; int ixA[8]; float4 syB[8]; int ixB[8];
#pragma unroll
    for (int k = 0; k < 8; k++) {
        syA[k] = g_ccsyn[p0 * CAPC + k]; ixA[k] = g_ccix[p0 * CAPC + k];
        syB[k] = g_ccsyn[p1 * CAPC + k]; ixB[k] = g_ccix[p1 * CAPC + k];
    }
    int cmx = max(cc0, cc1);
    for (int off = 16; off; off >>= 1)
        cmx = max(cmx, __shfl_xor_sync(FULL, cmx, off));
    const int cmreg = min(cmx, 8);

    float v0 = 0.f, v1 = 0.f;
    float2 pc0[UNF], pc1[UNF];
    float2 ss0 = g_ssum[(b * NT) * 96 + j0];
    float2 ss1 = g_ssum[(b * NT) * 96 + j1];
#pragma unroll
    for (int u = 0; u < UNF; u++) {
        pc0[u] = g_pcmd[((b * NT) * UNF + u) * CMDN + p0];
        pc1[u] = g_pcmd[((b * NT) * UNF + u) * CMDN + p1];
    }

    for (int s = 0; s < NT; s++) {
        const int sn = (s + 1 < NT) ? s + 1 : s;
        float2 nss0 = g_ssum[(b * NT + sn) * 96 + j0];
        float2 nss1 = g_ssum[(b * NT + sn) * 96 + j1];
        float2 npc0[UNF], npc1[UNF];
#pragma unroll
        for (int u = 0; u < UNF; u++) {
            npc0[u] = g_pcmd[((b * NT + sn) * UNF + u) * CMDN + p0];
            npc1[u] = g_pcmd[((b * NT + sn) * UNF + u) * CMDN + p1];
        }
        // bases include the constant half of the tanh-split sigmoid sums
        const float cn0 = gv0 + ss0.x + cb0.x;
        const float cd0 = cmt0 + gl0 + ss0.y + cb0.y + EPSF;
        const float cn1 = gv1 + ss1.x + cb1.x;
        const float cd1 = cmt1 + gl1 + ss1.y + cb1.y + EPSF;
#pragma unroll
        for (int u = 0; u < UNF; u++) {
            const int row = ((b * NT + s) * UNF + u) * CMDN;
            g_ctraj[row + p0] = v0;
            g_ctraj[row + p1] = v1;
            float na0 = 0.f, da0 = 0.f, na1 = 0.f, da1 = 0.f;
#pragma unroll
            for (int k = 0; k < 8; k++) {
                if (k >= cmreg) break;   // cmreg warp-uniform
                {
                    const int q = ixA[k];
                    float a  = __shfl_sync(FULL, v0, q & 31);
                    float bb = __shfl_sync(FULL, v1, q & 31);
                    float vp = (q < 32) ? a : bb;
                    float tt = tanhf_a(fmaf(syA[k].x, vp, -syA[k].y));
                    da0 = fmaf(syA[k].z, tt, da0);
                    na0 = fmaf(syA[k].w, tt, na0);
                }
                {
                    const int q = ixB[k];
                    float a  = __shfl_sync(FULL, v0, q & 31);
                    float bb = __shfl_sync(FULL, v1, q & 31);
                    float vp = (q < 32) ? a : bb;
                    float tt = tanhf_a(fmaf(syB[k].x, vp, -syB[k].y));
                    da1 = fmaf(syB[k].z, tt, da1);
                    na1 = fmaf(syB[k].w, tt, na1);
                }
            }
            for (int k = 8; k < cmx; k++) {   // rare tail
                {
                    float4 sy = g_ccsyn[p0 * CAPC + k];
                    const int q = g_ccix[p0 * CAPC + k];
                    float a  = __shfl_sync(FULL, v0, q & 31);
                    float bb = __shfl_sync(FULL, v1, q & 31);
                    float vp = (q < 32) ? a : bb;
                    float tt = tanhf_a(fmaf(sy.x, vp, -sy.y));
                    da0 = fmaf(sy.z, tt, da0);
                    na0 = fmaf(sy.w, tt, na0);
                }
                {
                    float4 sy = g_ccsyn[p1 * CAPC + k];
                    const int q = g_ccix[p1 * CAPC + k];
                    float a  = __shfl_sync(FULL, v0, q & 31);
                    float bb = __shfl_sync(FULL, v1, q & 31);
                    float vp = (q < 32) ? a : bb;
                    float tt = tanhf_a(fmaf(sy.x, vp, -sy.y));
                    da1 = fmaf(sy.z, tt, da1);
                    na1 = fmaf(sy.w, tt, na1);
                }
            }
            v0 = (fmaf(cmt0, v0, cn0) + pc0[u].x + na0) * rcpf(cd0 + pc0[u].y + da0);
            v1 = (fmaf(cmt1, v1, cn1) + pc1[u].x + na1) * rcpf(cd1 + pc1[u].y + da1);
        }
#pragma unroll
        for (int u = 0; u < UNF; u++) { pc0[u] = npc0[u]; pc1[u] = npc1[u]; }
        ss0 = nss0; ss1 = nss1;
    }
}

// ============ P4: motor affine coeffs: grid 1024 x 256, k-outer ==============
__global__ void __launch_bounds__(256)
kp4(const float* __restrict__ gleak, const float* __restrict__ vleak,
    const float* __restrict__ cm)
{
    __shared__ float trow[UNF][192];
    const int bs = blockIdx.x;
    const int t = threadIdx.x;
    for (int idx = t; idx < UNF * CMDN; idx += 256) {
        int u = idx >> 6, c = idx & 63;
        trow[u][c] = g_ctraj[(bs * UNF + u) * CMDN + c];
    }
    for (int idx = t; idx < UNF * INTERN; idx += 256) {
        int u = idx >> 7, i = idx & 127;
        trow[u][CMDN + i] = g_vtraj[bs * (UNF * INTERN) + idx];
    }
    __syncthreads();
    const int m = t >> 3, h = t & 7;
    const int cnt = min(g_mc[m], CAPM);
    const float cmt = cm[m] * (float)UNF;
    const float gl = gleak[m], vl = vleak[m];
    const float2 ssm = g_ssum[bs * 96 + m];
    float na[UNF], da[UNF];
#pragma unroll
    for (int u = 0; u < UNF; u++) { na[u] = 0.f; da[u] = 0.f; }
    for (int k = h; k < cnt; k += 8) {
        float4 sy = g_msyn[m * CAPM + k];
        const int ix = g_mtix[m * CAPM + k];
#pragma unroll
        for (int u = 0; u < UNF; u++) {
            float vp = trow[u][ix];
            float sg = rcpf(1.f + ex2f(fmaf(-sy.x, vp, sy.y)));
            da[u] = fmaf(sy.z, sg, da[u]);
            na[u] = fmaf(sy.w, sg, na[u]);
        }
    }
#pragma unroll
    for (int u = 0; u < UNF; u++) {
        float nu = na[u], du = da[u];
        nu += __shfl_xor_sync(0xffffffffu, nu, 1);
        nu += __shfl_xor_sync(0xffffffffu, nu, 2);
        nu += __shfl_xor_sync(0xffffffffu, nu, 4);
        du += __shfl_xor_sync(0xffffffffu, du, 1);
        du += __shfl_xor_sync(0xffffffffu, du, 2);
        du += __shfl_xor_sync(0xffffffffu, du, 4);
        if (h == 0) {
            float dinv = rcpf(cmt + gl + ssm.y + du + EPSF);
            g_mac[(bs * UNF + u) * MOTORN + m] =
                make_float2(cmt * dinv, (fmaf(gl, vl, ssm.x) + nu) * dinv);
        }
    }
}

// ============ P5: motor scan + output GEMV: grid 8 x 128 (warp = batch) ======
__global__ void __launch_bounds__(128)
kp5(const float* __restrict__ output_w, const float* __restrict__ output_b,
    const float* __restrict__ dense_w,  const float* __restrict__ dense_b,
    float* __restrict__ out)
{
    int badl = 0;
    for (int i = threadIdx.x; i < UNITS; i += 128) badl |= g_badv[i];
    if (__syncthreads_or(badl)) return;

    const int w = threadIdx.x >> 5, lane = threadIdx.x & 31;
    const int b = blockIdx.x * 4 + w;
    const float ow = output_w[lane], ob = output_b[lane];
    const float db = dense_b[lane];
    float dwc[32];
#pragma unroll
    for (int m = 0; m < 32; m++) dwc[m] = dense_w[m * OUTL + lane];

    float v = 0.f;
    float2 mc[UNF];
#pragma unroll
    for (int u = 0; u < UNF; u++)
        mc[u] = g_mac[((b * NT) * UNF + u) * MOTORN + lane];

    for (int s = 0; s < NT; s++) {
        const int sn = (s + 1 < NT) ? s + 1 : s;
        float2 nmc[UNF];
#pragma unroll
        for (int u = 0; u < UNF; u++)
            nmc[u] = g_mac[((b * NT + sn) * UNF + u) * MOTORN + lane];
#pragma unroll
        for (int u = 0; u < UNF; u++) v = fmaf(mc[u].x, v, mc[u].y);
        float ym = fmaf(v, ow, ob);
        float acc = db;
#pragma unroll
        for (int m = 0; m < 32; m++)
            acc = fmaf(__shfl_sync(0xffffffffu, ym, m), dwc[m], acc);
        out[(b * NT + s) * OUTL + lane] = acc;
#pragma unroll
        for (int u = 0; u < UNF; u++) mc[u] = nmc[u];
    }
}

// ============ dense fallback (any wiring; early-exit when fast path valid) ====
__global__ void __launch_bounds__(UNITS)
kfall(
    const float* __restrict__ inputs,
    const float* __restrict__ input_w, const float* __restrict__ input_b,
    const float* __restrict__ smu,  const float* __restrict__ ssig,
    const float* __restrict__ swt,  const float* __restrict__ serev,
    const float* __restrict__ smask,
    const float* __restrict__ mu,   const float* __restrict__ sig,
    const float* __restrict__ wt,   const float* __restrict__ erev,
    const float* __restrict__ mask,
    const float* __restrict__ gleak, const float* __restrict__ vleak,
    const float* __restrict__ cm,
    const float* __restrict__ output_w, const float* __restrict__ output_b,
    const float* __restrict__ dense_w,  const float* __restrict__ dense_b,
    float* __restrict__ out)
{
    const int t = threadIdx.x;
    int badl = g_badv[t];
    if (!__syncthreads_or(badl)) return;

    __shared__ float v0s[UNITS], v1s[UNITS], sx[SENS];
    const int b = blockIdx.x;
    const int j = t;
    float cmt = cm[j] * (float)UNF, gl = gleak[j], gv = gl * vleak[j];
    v0s[j] = 0.f;
    __syncthreads();
    float* cur = v0s; float* nxt = v1s;
    for (int s = 0; s < NT; s++) {
        if (t < SENS)
            sx[t] = fmaf(inputs[(b * NT + s) * SENS + t], input_w[t], input_b[t]);
        __syncthreads();
        float sn = 0.f, sd = 0.f;
        for (int i = 0; i < SENS; i++) {
            float m = smask[i * UNITS + j];
            if (m != 0.f) {
                float sg = ssig[i * UNITS + j];
                float sv = rcpf(1.f + ex2f(LOG2E * sg * (smu[i * UNITS + j] - sx[i])));
                float wm = swt[i * UNITS + j] * m;
                sd += wm * sv; sn += wm * serev[i * UNITS + j] * sv;
            }
        }
        for (int u = 0; u < UNF; u++) {
            float na = sn, da = sd;
            for (int i = 0; i < UNITS; i++) {
                float m = mask[i * UNITS + j];
                if (m != 0.f) {
                    float sg = sig[i * UNITS + j];
                    float sv = rcpf(1.f + ex2f(LOG2E * sg * (mu[i * UNITS + j] - cur[i])));
                    float wm = wt[i * UNITS + j] * m;
                    da += wm * sv; na += wm * erev[i * UNITS + j] * sv;
                }
            }
            nxt[j] = (fmaf(cmt, cur[j], gv) + na) * rcpf(cmt + gl + da + EPSF);
            __syncthreads();
            float* tmp = cur; cur = nxt; nxt = tmp;
        }
        if (t < OUTL) {
            float acc = dense_b[t];
            for (int m = 0; m < MOTORN; m++)
                acc = fmaf(fmaf(cur[m], output_w[m], output_b[m]),
                           dense_w[m * OUTL + t], acc);
            out[(b * NT + s) * OUTL + t] = acc;
        }
        __syncthreads();
    }
}

extern "C" void kernel_launch(void* const* d_in, const int* in_sizes, int n_in,
                              void* d_out, int out_size)
{
    const float* inputs   = (const float*)d_in[0];
    const float* input_w  = (const float*)d_in[1];
    const float* input_b  = (const float*)d_in[2];
    const float* smu      = (const float*)d_in[3];
    const float* ssig     = (const float*)d_in[4];
    const float* swt      = (const float*)d_in[5];
    const float* serev    = (const float*)d_in[6];
    const float* smask    = (const float*)d_in[7];
    const float* mu       = (const float*)d_in[8];
    const float* sig      = (const float*)d_in[9];
    const float* wt       = (const float*)d_in[10];
    const float* erev     = (const float*)d_in[11];
    const float* mask     = (const float*)d_in[12];
    const float* gleak    = (const float*)d_in[13];
    const float* vleak    = (const float*)d_in[14];
    const float* cm       = (const float*)d_in[15];
    const float* output_w = (const float*)d_in[16];
    const float* output_b = (const float*)d_in[17];
    const float* dense_w  = (const float*)d_in[18];
    const float* dense_b  = (const float*)d_in[19];
    float* out = (float*)d_out;

    kprep<<<UNITS, 32>>>(smu, ssig, swt, serev, smask, mu, sig, wt, erev, mask);
    kp1<<<NB * NT, 256>>>(inputs, input_w, input_b, gleak, vleak, cm);
    kiscan<<<NB, INTERN>>>();
    kp2<<<NB * NT, 256>>>();
    kp3<<<NB, 32>>>(gleak, vleak, cm);
    kp4<<<NB * NT, 256>>>(gleak, vleak, cm);
    kp5<<<8, 128>>>(output_w, output_b, dense_w, dense_b, out);
    kfall<<<NB, UNITS>>>(inputs, input_w, input_b,
                         smu, ssig, swt, serev, smask,
                         mu, sig, wt, erev, mask,
                         gleak, vleak, cm,
                         output_w, output_b, dense_w, dense_b, out);
}